// round 15
// baseline (speedup 1.0000x reference)
#include <cuda_runtime.h>
#include <cuda_bf16.h>

// ContourIntegrationLayer: depthwise 3x3 conv (center tap zeroed) + residual.
// x: [B=32, H=56, W=56, C=256] fp32 NHWC ; kernel: [3,3,256] fp32.
//
// R15: SYNC-FREE cp.async pipeline. Each thread stages into wslot-private
// smem exactly the 4 chunks (slices jw..jw+3 at its c4 lane) that it alone
// consumes -> zero cross-thread deps -> no __syncthreads in the loop;
// per-thread wait_group is the only sync. 8 warps free-run as independent
// pipelines. Interior slices duplicated across 2 wslots (L2 absorbs).
// NS=4 ring (64KB dynamic smem), prefetch row i+3, wait_group 3.

#define BD 32
#define HD 56
#define WD 56
#define C4D 64                 // 256/4 float4 lanes
#define H_SEG 14
#define W_BLK 8                // w per block
#define WSLOT 4
#define NS 4                   // ring stages
#define ROWSTRIDE (WD * C4D)   // 3584 float4 per image row
// stage layout: [NS][WSLOT][4 slices][C4D] float4
#define STAGE_F4 (WSLOT * 4 * C4D)           // 1024 float4 = 16KB per row-stage
#define SMEM_BYTES (NS * STAGE_F4 * 16)      // 65536

__device__ __forceinline__ void cp16(float4* dst_smem, const float4* src) {
    unsigned d = (unsigned)__cvta_generic_to_shared(dst_smem);
    asm volatile("cp.async.cg.shared.global [%0], [%1], 16;" :: "r"(d), "l"(src));
}
#define CP_COMMIT() asm volatile("cp.async.commit_group;" ::: "memory")
#define CP_WAIT3()  asm volatile("cp.async.wait_group 3;" ::: "memory")

__device__ __forceinline__ void fma4(float4& a, const float4& k, const float4& v) {
    a.x = fmaf(k.x, v.x, a.x);
    a.y = fmaf(k.y, v.y, a.y);
    a.z = fmaf(k.z, v.z, a.z);
    a.w = fmaf(k.w, v.w, a.w);
}
__device__ __forceinline__ void add4(float4& a, const float4& v) {
    a.x += v.x; a.y += v.y; a.z += v.z; a.w += v.w;
}

__global__ __launch_bounds__(256, 3)
void contour_integration_kernel(const float* __restrict__ x,
                                const float* __restrict__ ker,
                                float* __restrict__ out) {
    extern __shared__ __align__(16) float4 stg[];   // [NS][WSLOT][4][C4D]

    const int c4    = threadIdx.x;              // 0..63
    const int wslot = threadIdx.y;              // 0..3
    const int w0    = blockIdx.x * W_BLK;
    const int h0    = blockIdx.y * H_SEG;
    const int b     = blockIdx.z;

    const float4 zf = make_float4(0.f, 0.f, 0.f, 0.f);

    const int jw = 2 * wslot;                   // local w of first output
    // This thread's 4 source columns: absolute w = w0 + jw - 1 + s, s=0..3.
    // Its private stage slots: stg[stage][wslot][s][c4].
    const int tbase = (wslot * 4) * C4D + c4;   // slot s at tbase + s*C4D

    // Validity per slice (uniform within a warp: wslot, w0 are warp-uniform).
    const int wa0 = w0 + jw - 1;
    bool v[4];
    const float4* src[4];
    #pragma unroll
    for (int s = 0; s < 4; ++s) {
        const int wa = wa0 + s;
        v[s] = (wa >= 0) && (wa < WD);
        src[s] = (const float4*)x + ((b * HD) * WD + (v[s] ? wa : 0)) * C4D + c4;
    }

    // Zero the stage slots cp will never write (this thread's own slots ->
    // no barrier needed; boundary wslots only).
    #pragma unroll
    for (int s = 0; s < 4; ++s) {
        if (!v[s]) {
            #pragma unroll
            for (int st = 0; st < NS; ++st)
                stg[st * STAGE_F4 + tbase + s * C4D] = zf;
        }
    }

    // Uniform taps (center (1,1) excluded by construction).
    const float4* kp = (const float4*)ker;
    const float4 k00 = kp[0 * C4D + c4];
    const float4 k01 = kp[1 * C4D + c4];
    const float4 k02 = kp[2 * C4D + c4];
    const float4 k10 = kp[3 * C4D + c4];
    const float4 k12 = kp[5 * C4D + c4];
    const float4 k20 = kp[6 * C4D + c4];
    const float4 k21 = kp[7 * C4D + c4];
    const float4 k22 = kp[8 * C4D + c4];

    const int out_b0 = ((b * HD) * WD + (w0 + jw)) * C4D + c4;
    float4* op = (float4*)out;

    // Prologue: rows h0-1, h0, h0+1 into stages 0,1,2 (three commit groups).
    #pragma unroll
    for (int i = 0; i < 3; ++i) {
        const int r = h0 - 1 + i;
        if (r >= 0) {                           // r < HD always here
            const int ro = r * ROWSTRIDE;
            float4* dst = stg + i * STAGE_F4 + tbase;
            #pragma unroll
            for (int s = 0; s < 4; ++s)
                if (v[s]) cp16(dst + s * C4D, src[s] + ro);
        }
        CP_COMMIT();
    }

    float4 a00 = zf, a10 = zf;   // partials for w = w0+jw
    float4 a01 = zf, a11 = zf;   // partials for w = w0+jw+1

    // Consume input rows r = h0-1+i, i = 0..H_SEG+1 (16 rows). NO BARRIERS.
    #pragma unroll
    for (int i = 0; i <= H_SEG + 1; ++i) {
        // Prefetch row i+3 into stage (i+3)%NS (that stage was last read at
        // iter i-1; its LDS fed FMAs issued before this cp in program order).
        if (i + 3 <= H_SEG + 1) {
            const int rn = h0 + 2 + i;
            if (rn < HD) {
                const int ro = rn * ROWSTRIDE;
                float4* dst = stg + ((i + 3) % NS) * STAGE_F4 + tbase;
                #pragma unroll
                for (int s = 0; s < 4; ++s)
                    if (v[s]) cp16(dst + s * C4D, src[s] + ro);
            }
        }
        CP_COMMIT();
        CP_WAIT3();                            // this thread's row i landed

        const int r = h0 - 1 + i;
        float4 xs0, xs1, xs2, xs3;
        if (r >= 0 && r < HD) {
            const float4* sp = stg + (i % NS) * STAGE_F4 + tbase;
            xs0 = sp[0]; xs1 = sp[C4D]; xs2 = sp[2 * C4D]; xs3 = sp[3 * C4D];
        } else {
            xs0 = zf; xs1 = zf; xs2 = zf; xs3 = zf;
        }

        // bottom taps of row r close out[r-1] for both w.
        if (i >= 2) {
            float4 o0 = a00;
            fma4(o0, k20, xs0); fma4(o0, k21, xs1); fma4(o0, k22, xs2);
            float4 o1 = a01;
            fma4(o1, k20, xs1); fma4(o1, k21, xs2); fma4(o1, k22, xs3);
            const int ob = out_b0 + (r - 1) * ROWSTRIDE;
            __stcs(op + ob, o0);
            __stcs(op + ob + C4D, o1);
        }

        // advance partials: mid taps + residual -> out[r]; top taps -> out[r+1]
        float4 A0 = a10;
        add4(A0, xs1);
        fma4(A0, k10, xs0); fma4(A0, k12, xs2);
        float4 B0 = zf;
        fma4(B0, k00, xs0); fma4(B0, k01, xs1); fma4(B0, k02, xs2);
        a00 = A0; a10 = B0;

        float4 A1 = a11;
        add4(A1, xs2);
        fma4(A1, k10, xs1); fma4(A1, k12, xs3);
        float4 B1 = zf;
        fma4(B1, k00, xs1); fma4(B1, k01, xs2); fma4(B1, k02, xs3);
        a01 = A1; a11 = B1;
    }
}

extern "C" void kernel_launch(void* const* d_in, const int* in_sizes, int n_in,
                              void* d_out, int out_size) {
    const float* x   = (const float*)d_in[0];   // [32,56,56,256]
    const float* ker = (const float*)d_in[1];   // [3,3,256]
    float*       outp = (float*)d_out;

    cudaFuncSetAttribute(contour_integration_kernel,
                         cudaFuncAttributeMaxDynamicSharedMemorySize, SMEM_BYTES);

    dim3 block(C4D, WSLOT);                     // 64 x 4 = 256 threads
    dim3 grid(WD / W_BLK, HD / H_SEG, BD);      // 7 x 4 x 32 = 896 blocks
    contour_integration_kernel<<<grid, block, SMEM_BYTES>>>(x, ker, outp);
}